// round 5
// baseline (speedup 1.0000x reference)
#include <cuda_runtime.h>
#include <cstdint>

// Problem constants
#define NX    2000
#define NZ    4
#define TT    16          // number of selected time steps
#define K2    24000       // nr*nx*nz = 3*2000*4
#define NJ    8000        // nz*nx
#define NXR   4000        // nx * NR_IN rows of the relation GEMM
#define KREL  2000        // K of the relation GEMM

typedef unsigned long long ull;

// f32x2 packed math (Blackwell)
#define FMA2(d, a, b, c) asm("fma.rn.f32x2 %0, %1, %2, %3;" : "=l"(d) : "l"(a), "l"(b), "l"(c))
#define ADD2(d, a, b)    asm("add.rn.f32x2 %0, %1, %2;"     : "=l"(d) : "l"(a), "l"(b))
#define DUP2(d, s)       asm("mov.b64 %0, {%1, %1};"        : "=l"(d) : "r"(__float_as_uint(s)))

static __device__ __forceinline__ float2 u2f(ull v) {
    float2 r;
    r.x = __uint_as_float((unsigned)(v & 0xffffffffu));
    r.y = __uint_as_float((unsigned)(v >> 32));
    return r;
}

// z_ctx scratch, stored t-pair-interleaved: g_zp[tp*K2 + k] = (zctx[2tp][k], zctx[2tp+1][k])
// 8 * 24000 float2 = 1.5 MB
__device__ __align__(16) float2 g_zp[8 * K2];

// ---------------------------------------------------------------------------
// Kernel 1a: identity relation slice (k in [0, 8000)): zctx[t][x*4+z] = factors[t_idx[t]][x][z]
// ---------------------------------------------------------------------------
__global__ void k_identity(const float* __restrict__ factors,
                           const int* __restrict__ t_idx) {
    int idx = blockIdx.x * blockDim.x + threadIdx.x;   // [0, 8*8000)
    if (idx >= 8 * NJ) return;
    int tp = idx / NJ;
    int k  = idx - tp * NJ;
    int ti0 = __ldg(t_idx + 2 * tp);
    int ti1 = __ldg(t_idx + 2 * tp + 1);
    float2 v;
    v.x = __ldg(factors + ti0 * NJ + k);
    v.y = __ldg(factors + ti1 * NJ + k);
    g_zp[tp * K2 + k] = v;
}

// ---------------------------------------------------------------------------
// Kernel 1b: relation GEMM.  C[xr][t*4+z] = sum_y relations_flat[xr][y] * factors[ti[t]][y][z]
// relations (2000,2,2000) row-major == A (4000, 2000) row-major; xr = x*2 + rin.
// Result scattered into g_zp at k = (rin+1)*8000 + x*4 + z.
// Tile: 32 rows x 16 t-cols per CTA (256 threads), y-chunks of 96.
// ---------------------------------------------------------------------------
__global__ __launch_bounds__(256) void k_relgemm(const float* __restrict__ A,
                                                 const float* __restrict__ factors,
                                                 const int* __restrict__ t_idx) {
    __shared__ float4 As4[32 * 24];    // 32 rows x 96 y  (12 KB)
    __shared__ float4 Bs4[96 * 16];    // 96 y x 16 t (float4 over z)  (24 KB)

    const int tid = threadIdx.x;
    const int xr0 = blockIdx.x * 32;
    const int a = tid >> 4;        // 0..15 -> rows 2a, 2a+1
    const int t = tid & 15;        // 0..15

    ull acc[2][2];                 // [row r][z-pair]
    acc[0][0] = acc[0][1] = acc[1][0] = acc[1][1] = 0ull;

    const float*      Asf = (const float*)As4;
    const ulonglong2* Bsu = (const ulonglong2*)Bs4;

    for (int yc = 0; yc < 2016; yc += 96) {
        __syncthreads();
        // load A chunk: 32 rows x 96 floats = 768 float4
        for (int i = tid; i < 768; i += 256) {
            int r  = i / 24;
            int c4 = i - r * 24;
            int y  = yc + c4 * 4;
            float4 v;
            if (y + 3 < KREL) {
                v = *(const float4*)(A + (xr0 + r) * KREL + y);
            } else {
                v.x = (y + 0 < KREL) ? A[(xr0 + r) * KREL + y + 0] : 0.0f;
                v.y = (y + 1 < KREL) ? A[(xr0 + r) * KREL + y + 1] : 0.0f;
                v.z = (y + 2 < KREL) ? A[(xr0 + r) * KREL + y + 2] : 0.0f;
                v.w = (y + 3 < KREL) ? A[(xr0 + r) * KREL + y + 3] : 0.0f;
            }
            As4[r * 24 + c4] = v;
        }
        // load B chunk: 16 t x 96 y float4 (z contiguous)
        const float4* f4 = (const float4*)factors;
        for (int i = tid; i < 1536; i += 256) {
            int tt = i / 96;
            int y  = i - tt * 96;
            int yy = yc + y;
            float4 v = make_float4(0.f, 0.f, 0.f, 0.f);
            if (yy < KREL) {
                int ti = __ldg(t_idx + tt);
                v = f4[ti * (NJ / 4) + yy];
            }
            Bs4[y * 16 + tt] = v;
        }
        __syncthreads();

        #pragma unroll 4
        for (int y = 0; y < 96; ++y) {
            float a0 = Asf[(2 * a)     * 96 + y];
            float a1 = Asf[(2 * a + 1) * 96 + y];
            ull a0d, a1d;
            DUP2(a0d, a0);
            DUP2(a1d, a1);
            ulonglong2 bv = Bsu[y * 16 + t];  // (z0,z1),(z2,z3)
            FMA2(acc[0][0], a0d, bv.x, acc[0][0]);
            FMA2(acc[0][1], a0d, bv.y, acc[0][1]);
            FMA2(acc[1][0], a1d, bv.x, acc[1][0]);
            FMA2(acc[1][1], a1d, bv.y, acc[1][1]);
        }
    }

    // scatter to g_zp (float view): offset(tp,k,h) = (tp*K2 + k)*2 + h
    float* gzf = (float*)g_zp;
    const int tp = t >> 1;
    const int h  = t & 1;
    #pragma unroll
    for (int r = 0; r < 2; ++r) {
        int xr  = xr0 + 2 * a + r;
        int x   = xr >> 1;
        int rin = xr & 1;
        int kb  = (rin + 1) * NJ + x * 4;
        float2 v0 = u2f(acc[r][0]);
        float2 v1 = u2f(acc[r][1]);
        gzf[(tp * K2 + kb + 0) * 2 + h] = v0.x;
        gzf[(tp * K2 + kb + 1) * 2 + h] = v0.y;
        gzf[(tp * K2 + kb + 2) * 2 + h] = v1.x;
        gzf[(tp * K2 + kb + 3) * 2 + h] = v1.y;
    }
}

// ---------------------------------------------------------------------------
// Kernel 2: out[t][j] = tanh( sum_k zctx[t][k] * W[j][k] + b[j] )
// M=16, N=8000, K=24000.  DRAM-bound on W (768 MB).
// 143 CTAs x 448 threads (14 warps). Each warp owns 4 j rows; lane<->k (stride 32).
// z chunk (8 t-pairs x 2400 k) in SMEM (150 KB), conflict-free LDS.64 reads.
// Depth-2 W prefetch pipeline; f32x2 accumulate; butterfly f32x2 reduce.
// ---------------------------------------------------------------------------
#define KC     2400
#define STEPS  75        // KC / 32
#define NCHUNK 10        // K2 / KC
#define TPB2   448
#define JCTA   56        // 14 warps * 4 j
#define GSTOT  750       // K2 / 32

// float4 accounting for the z staging:
//   g_zp as float4: per tp-row = K2/2 = 12000 float4; per chunk per tp = KC/2 = 1200 float4.
#define ZROW4   (K2 / 2)      // 12000
#define ZCH4    (KC / 2)      // 1200
#define ZTOT4   (8 * ZCH4)    // 9600 float4 per chunk

__global__ __launch_bounds__(TPB2, 1) void k_biggemm(const float* __restrict__ W,
                                                     const float* __restrict__ b,
                                                     float* __restrict__ out) {
    extern __shared__ float2 zs[];     // [8][KC]
    const int tid = threadIdx.x;
    const int w   = tid >> 5;
    const int l   = tid & 31;
    const int jbase = blockIdx.x * JCTA + w * 4;

    const float* Wr[4];
    #pragma unroll
    for (int jj = 0; jj < 4; ++jj) {
        int j = jbase + jj;
        Wr[jj] = W + (long)min(j, NJ - 1) * K2;
    }

    ull acc[4][8];
    #pragma unroll
    for (int jj = 0; jj < 4; ++jj)
        #pragma unroll
        for (int tp = 0; tp < 8; ++tp) acc[jj][tp] = 0ull;

    // prefetch pipeline: w0 = step gs, w1 = step gs+1
    float w0[4], w1[4];
    #pragma unroll
    for (int jj = 0; jj < 4; ++jj) {
        w0[jj] = __ldg(Wr[jj] + l);
        w1[jj] = __ldg(Wr[jj] + 32 + l);
    }

    const ull* zsu = (const ull*)zs;
    const float4* gz4 = (const float4*)g_zp;
    float4* zs4 = (float4*)zs;

    for (int c = 0; c < NCHUNK; ++c) {
        __syncthreads();
        // load z chunk: 8 tp-rows x 1200 float4 (= 8 x 2400 float2)
        for (int i = tid; i < ZTOT4; i += TPB2) {
            int tp = i / ZCH4;
            int m  = i - tp * ZCH4;
            zs4[tp * ZCH4 + m] = gz4[tp * ZROW4 + c * ZCH4 + m];
        }
        __syncthreads();

        const int gsbase = c * STEPS;
        #pragma unroll 5
        for (int s = 0; s < STEPS; ++s) {
            const int kk = s * 32 + l;
            ull z2[8];
            #pragma unroll
            for (int tp = 0; tp < 8; ++tp) z2[tp] = zsu[tp * KC + kk];

            // prefetch step gs+2
            const int gs2 = gsbase + s + 2;
            const int kg2 = gs2 * 32 + l;
            float wn[4];
            #pragma unroll
            for (int jj = 0; jj < 4; ++jj)
                wn[jj] = (gs2 < GSTOT) ? __ldg(Wr[jj] + kg2) : 0.0f;

            #pragma unroll
            for (int jj = 0; jj < 4; ++jj) {
                ull w2;
                DUP2(w2, w0[jj]);
                #pragma unroll
                for (int tp = 0; tp < 8; ++tp)
                    FMA2(acc[jj][tp], w2, z2[tp], acc[jj][tp]);
            }
            #pragma unroll
            for (int jj = 0; jj < 4; ++jj) { w0[jj] = w1[jj]; w1[jj] = wn[jj]; }
        }
    }

    // butterfly reduce across lanes (all lanes end with full sums)
    #pragma unroll
    for (int off = 16; off; off >>= 1) {
        #pragma unroll
        for (int jj = 0; jj < 4; ++jj)
            #pragma unroll
            for (int tp = 0; tp < 8; ++tp) {
                ull o = __shfl_xor_sync(0xffffffffu, acc[jj][tp], off);
                ADD2(acc[jj][tp], acc[jj][tp], o);
            }
    }

    // epilogue: lane l < 16 handles t = l
    if (l < 16) {
        const int tp = l >> 1;
        const int h  = l & 1;
        #pragma unroll
        for (int jj = 0; jj < 4; ++jj) {
            int j = jbase + jj;
            if (j < NJ) {
                float2 f = u2f(acc[jj][tp]);
                float s = h ? f.y : f.x;
                out[l * NJ + j] = tanhf(s + __ldg(b + j));
            }
        }
    }
}

// ---------------------------------------------------------------------------
extern "C" void kernel_launch(void* const* d_in, const int* in_sizes, int n_in,
                              void* d_out, int out_size) {
    const float* relations = (const float*)d_in[0];  // (2000, 2, 2000)
    const float* factors   = (const float*)d_in[1];  // (200, 2000, 4)
    const float* W_dyn     = (const float*)d_in[2];  // (8000, 24000)
    const float* b_dyn     = (const float*)d_in[3];  // (8000,)
    const int*   t_idx     = (const int*)d_in[4];    // (16,) int32
    float* out = (float*)d_out;                      // (16, 8000)

    // cudaFuncSetAttribute is a host-side, non-stream call; safe under capture.
    cudaFuncSetAttribute(k_biggemm, cudaFuncAttributeMaxDynamicSharedMemorySize,
                         8 * KC * (int)sizeof(float2));

    // 1a: identity slice of z_ctx
    k_identity<<<(8 * NJ + 255) / 256, 256>>>(factors, t_idx);
    // 1b: relation GEMM slices of z_ctx
    k_relgemm<<<NXR / 32, 256>>>(relations, factors, t_idx);
    // 2: big fused GEMM + bias + tanh
    k_biggemm<<<(NJ + JCTA - 1) / JCTA, TPB2, 8 * KC * (int)sizeof(float2)>>>(W_dyn, b_dyn, out);
}